// round 1
// baseline (speedup 1.0000x reference)
#include <cuda_runtime.h>
#include <cuda_bf16.h>

#define BB    2048
#define DM    128
#define FF    12800
#define NDLLM 768
#define NDFF  256
#define NE    8
#define NGIN  13569          // 768 + 1 + 12800
#define GATE_SPLIT 8
#define KSEG_GATE  1697      // ceil(13569/8)
#define GEN_SPLIT  8
#define KSEG_GEN   1600      // 12800/8

// scratch (static device globals; no allocation allowed)
__device__ float g_gate_partial[(size_t)GATE_SPLIT * BB * NDFF]; // 16.8 MB
__device__ float g_gen_partial[(size_t)GEN_SPLIT * BB * DM];     // 8.4 MB
__device__ float g_combined[(size_t)BB * DM];                    // 1 MB
__device__ int   g_counts[NE];
__device__ int   g_list[NE * BB];
__device__ float g_gateval[NE * BB];

// ---------------------------------------------------------------------------
// 0) zero the accumulators that are atomically built each call
// ---------------------------------------------------------------------------
__global__ void init_zero_kernel() {
    int i = blockIdx.x * blockDim.x + threadIdx.x;
    if (i < BB * DM) g_combined[i] = 0.0f;
    if (i < NE) g_counts[i] = 0;
}

// ---------------------------------------------------------------------------
// 1) gate GEMM: partial[s][b][j] = sum_{k in seg s} gin[b][k] * Wg1[k][j]
//    gin = concat(DKP[768], cycle[1], xf[12800]) assembled on the fly.
//    BM=32 tokens, BN=256 (all of DFF), BK=32, split-K=8 -> 512 CTAs
// ---------------------------------------------------------------------------
__global__ void __launch_bounds__(256)
gate_gemm_kernel(const float* __restrict__ xf, const float* __restrict__ cyc,
                 const float* __restrict__ dkp, const float* __restrict__ Wg1) {
    __shared__ float As[32][33];    // [k][m], padded
    __shared__ float Bs[32][256];   // [k][n]
    const int bm   = blockIdx.x * 32;
    const int s    = blockIdx.y;
    const int kbeg = s * KSEG_GATE;
    const int kend = min(NGIN, kbeg + KSEG_GATE);
    const int tid  = threadIdx.x;
    const int tx   = tid & 31;      // col lane: covers cols tx + 32*j
    const int ty   = tid >> 5;      // row group: covers tokens ty*4 .. ty*4+3

    float acc[4][8];
#pragma unroll
    for (int i = 0; i < 4; i++)
#pragma unroll
        for (int j = 0; j < 8; j++) acc[i][j] = 0.0f;

    for (int k0 = kbeg; k0 < kend; k0 += 32) {
        // A tile: 32 tokens x 32 k (gathered from virtual concat)
        {
            const int kk = tid & 31;
            const int mbase = tid >> 5;
            const int k = k0 + kk;
#pragma unroll
            for (int i = 0; i < 4; i++) {
                const int mm = mbase + i * 8;
                const int b = bm + mm;
                float v = 0.0f;
                if (k < kend) {
                    if (k < NDLLM)       v = dkp[(size_t)b * NDLLM + k];
                    else if (k == NDLLM) v = cyc[b];
                    else                 v = xf[(size_t)b * FF + (k - NDLLM - 1)];
                }
                As[kk][mm] = v;
            }
        }
        // B tile: 32 x 256 via float4
        {
            const int c4 = tid & 63;        // 0..63 -> cols c4*4..c4*4+3
            const int rbase = tid >> 6;     // 0..3
#pragma unroll
            for (int p = 0; p < 8; p++) {
                const int r = rbase + p * 4;
                const int k = k0 + r;
                float4 v = make_float4(0.f, 0.f, 0.f, 0.f);
                if (k < kend)
                    v = *reinterpret_cast<const float4*>(&Wg1[(size_t)k * NDFF + c4 * 4]);
                *reinterpret_cast<float4*>(&Bs[r][c4 * 4]) = v;
            }
        }
        __syncthreads();
#pragma unroll
        for (int kk = 0; kk < 32; kk++) {
            const float a0 = As[kk][ty * 4 + 0];
            const float a1 = As[kk][ty * 4 + 1];
            const float a2 = As[kk][ty * 4 + 2];
            const float a3 = As[kk][ty * 4 + 3];
#pragma unroll
            for (int j = 0; j < 8; j++) {
                const float bv = Bs[kk][tx + 32 * j];   // bank = tx, conflict-free
                acc[0][j] += a0 * bv;
                acc[1][j] += a1 * bv;
                acc[2][j] += a2 * bv;
                acc[3][j] += a3 * bv;
            }
        }
        __syncthreads();
    }
#pragma unroll
    for (int i = 0; i < 4; i++) {
        const int t = bm + ty * 4 + i;
#pragma unroll
        for (int j = 0; j < 8; j++)
            g_gate_partial[((size_t)s * BB + t) * NDFF + tx + 32 * j] = acc[i][j];
    }
}

// ---------------------------------------------------------------------------
// 2) gate epilogue: reduce split-K partials, +bg1, gelu(tanh approx),
//    @Wg2 + bg2, softmax over all 8, top-2 (lower-index tie-break),
//    renormalize (+1e-9), build per-expert dispatch lists.
//    One warp per token.
// ---------------------------------------------------------------------------
__global__ void __launch_bounds__(256)
gate_epilogue_kernel(const float* __restrict__ bg1, const float* __restrict__ Wg2,
                     const float* __restrict__ bg2) {
    const int warp = threadIdx.x >> 5;
    const int lane = threadIdx.x & 31;
    const int t = blockIdx.x * 8 + warp;
    if (t >= BB) return;

    float h[8];
#pragma unroll
    for (int j = 0; j < 8; j++) {
        const int c = lane + 32 * j;
        float v = bg1[c];
#pragma unroll
        for (int s = 0; s < GATE_SPLIT; s++)
            v += g_gate_partial[((size_t)s * BB + t) * NDFF + c];
        // JAX default gelu: approximate=True (tanh)
        const float x = v;
        const float inner = 0.7978845608028654f * (x + 0.044715f * x * x * x);
        h[j] = 0.5f * x * (1.0f + tanhf(inner));
    }
    float le[NE];
#pragma unroll
    for (int e = 0; e < NE; e++) {
        float s = 0.0f;
#pragma unroll
        for (int j = 0; j < 8; j++)
            s += h[j] * Wg2[(size_t)(lane + 32 * j) * NE + e];
#pragma unroll
        for (int o = 16; o > 0; o >>= 1)
            s += __shfl_xor_sync(0xffffffffu, s, o);
        le[e] = s;
    }
    if (lane == 0) {
        float logits[NE];
#pragma unroll
        for (int e = 0; e < NE; e++) logits[e] = le[e] + bg2[e];
        float mx = logits[0];
#pragma unroll
        for (int e = 1; e < NE; e++) mx = fmaxf(mx, logits[e]);
        float p[NE];
        float sum = 0.0f;
#pragma unroll
        for (int e = 0; e < NE; e++) { p[e] = __expf(logits[e] - mx) ; p[e] = expf(logits[e] - mx); sum += p[e]; }
#pragma unroll
        for (int e = 0; e < NE; e++) p[e] /= sum;
        int i1 = 0;
#pragma unroll
        for (int e = 1; e < NE; e++) if (logits[e] > logits[i1]) i1 = e;
        int i2 = (i1 == 0) ? 1 : 0;
#pragma unroll
        for (int e = 0; e < NE; e++)
            if (e != i1 && logits[e] > logits[i2]) i2 = e;
        const float denom = p[i1] + p[i2] + 1e-9f;
        const float g1 = p[i1] / denom;
        const float g2 = p[i2] / denom;
        int pos1 = atomicAdd(&g_counts[i1], 1);
        g_list[i1 * BB + pos1] = t;
        g_gateval[i1 * BB + pos1] = g1;
        int pos2 = atomicAdd(&g_counts[i2], 1);
        g_list[i2 * BB + pos2] = t;
        g_gateval[i2 * BB + pos2] = g2;
    }
}

// ---------------------------------------------------------------------------
// 3) general GEMM: gen_partial[s][b][d] = sum_{k in seg} xf[b][k]*Wgen[k][d]
//    BM=32, BN=128, BK=32, split-K=8 -> 512 CTAs
// ---------------------------------------------------------------------------
__global__ void __launch_bounds__(256)
general_gemm_kernel(const float* __restrict__ xf, const float* __restrict__ Wgen) {
    __shared__ float As[32][33];
    __shared__ float Bs[32][128];
    const int bm = blockIdx.x * 32;
    const int s = blockIdx.y;
    const int kbeg = s * KSEG_GEN;
    const int kend = kbeg + KSEG_GEN;
    const int tid = threadIdx.x;
    const int tx = tid & 31;
    const int ty = tid >> 5;

    float acc[4][4];
#pragma unroll
    for (int i = 0; i < 4; i++)
#pragma unroll
        for (int j = 0; j < 4; j++) acc[i][j] = 0.0f;

    for (int k0 = kbeg; k0 < kend; k0 += 32) {
        {
            const int kk = tid & 31;
            const int mbase = tid >> 5;
#pragma unroll
            for (int i = 0; i < 4; i++) {
                const int mm = mbase + i * 8;
                As[kk][mm] = xf[(size_t)(bm + mm) * FF + k0 + kk];
            }
        }
        {
            const int c4 = tid & 31;
            const int rbase = tid >> 5;
#pragma unroll
            for (int p = 0; p < 4; p++) {
                const int r = rbase + p * 8;
                float4 v = *reinterpret_cast<const float4*>(&Wgen[(size_t)(k0 + r) * DM + c4 * 4]);
                *reinterpret_cast<float4*>(&Bs[r][c4 * 4]) = v;
            }
        }
        __syncthreads();
#pragma unroll
        for (int kk = 0; kk < 32; kk++) {
            const float a0 = As[kk][ty * 4 + 0];
            const float a1 = As[kk][ty * 4 + 1];
            const float a2 = As[kk][ty * 4 + 2];
            const float a3 = As[kk][ty * 4 + 3];
#pragma unroll
            for (int j = 0; j < 4; j++) {
                const float bv = Bs[kk][tx + 32 * j];
                acc[0][j] += a0 * bv;
                acc[1][j] += a1 * bv;
                acc[2][j] += a2 * bv;
                acc[3][j] += a3 * bv;
            }
        }
        __syncthreads();
    }
#pragma unroll
    for (int i = 0; i < 4; i++) {
        const int t = bm + ty * 4 + i;
#pragma unroll
        for (int j = 0; j < 4; j++)
            g_gen_partial[((size_t)s * BB + t) * DM + tx + 32 * j] = acc[i][j];
    }
}

// ---------------------------------------------------------------------------
// 4) expert GEMMs (gathered): for each expert e, for its token list,
//    combined[t][d] += gate * (xf[t] . We[e][:,d] + be[e][d])
//    Exactly 2 atomic contributions per (t,d): order-independent fp32 sum.
// ---------------------------------------------------------------------------
__global__ void __launch_bounds__(256)
expert_gemm_kernel(const float* __restrict__ xf, const float* __restrict__ We,
                   const float* __restrict__ be) {
    __shared__ float As[32][33];
    __shared__ float Bs[32][128];
    __shared__ int   s_tok[32];
    __shared__ float s_gate[32];
    const int e = blockIdx.y;
    const int n = g_counts[e];
    const int t0 = blockIdx.x * 32;
    if (t0 >= n) return;

    const int tid = threadIdx.x;
    if (tid < 32) {
        const int idx = t0 + tid;
        s_tok[tid]  = (idx < n) ? g_list[e * BB + idx] : -1;
        s_gate[tid] = (idx < n) ? g_gateval[e * BB + idx] : 0.0f;
    }
    __syncthreads();

    const int tx = tid & 31;
    const int ty = tid >> 5;
    const float* W = We + (size_t)e * FF * DM;

    float acc[4][4];
#pragma unroll
    for (int i = 0; i < 4; i++)
#pragma unroll
        for (int j = 0; j < 4; j++) acc[i][j] = 0.0f;

    for (int k0 = 0; k0 < FF; k0 += 32) {
        {
            const int kk = tid & 31;
            const int mbase = tid >> 5;
#pragma unroll
            for (int i = 0; i < 4; i++) {
                const int mm = mbase + i * 8;
                const int tok = s_tok[mm];
                As[kk][mm] = (tok >= 0) ? xf[(size_t)tok * FF + k0 + kk] : 0.0f;
            }
        }
        {
            const int c4 = tid & 31;
            const int rbase = tid >> 5;
#pragma unroll
            for (int p = 0; p < 4; p++) {
                const int r = rbase + p * 8;
                float4 v = *reinterpret_cast<const float4*>(&W[(size_t)(k0 + r) * DM + c4 * 4]);
                *reinterpret_cast<float4*>(&Bs[r][c4 * 4]) = v;
            }
        }
        __syncthreads();
#pragma unroll
        for (int kk = 0; kk < 32; kk++) {
            const float a0 = As[kk][ty * 4 + 0];
            const float a1 = As[kk][ty * 4 + 1];
            const float a2 = As[kk][ty * 4 + 2];
            const float a3 = As[kk][ty * 4 + 3];
#pragma unroll
            for (int j = 0; j < 4; j++) {
                const float bv = Bs[kk][tx + 32 * j];
                acc[0][j] += a0 * bv;
                acc[1][j] += a1 * bv;
                acc[2][j] += a2 * bv;
                acc[3][j] += a3 * bv;
            }
        }
        __syncthreads();
    }
#pragma unroll
    for (int i = 0; i < 4; i++) {
        const int mm = ty * 4 + i;
        const int tok = s_tok[mm];
        if (tok < 0) continue;
        const float g = s_gate[mm];
#pragma unroll
        for (int j = 0; j < 4; j++) {
            const int c = tx + 32 * j;
            atomicAdd(&g_combined[(size_t)tok * DM + c], g * (acc[i][j] + be[e * DM + c]));
        }
    }
}

// ---------------------------------------------------------------------------
// 5) finalize: out = (sum split-K general partials + bgen) + f32(bf16(combined))
//    bf16 cast is RNE, matching jnp astype(bfloat16).
// ---------------------------------------------------------------------------
__global__ void finalize_kernel(const float* __restrict__ bgen, float* __restrict__ out) {
    const int i = blockIdx.x * blockDim.x + threadIdx.x;
    if (i >= BB * DM) return;
    const int c = i & (DM - 1);
    float gen = bgen[c];
#pragma unroll
    for (int s = 0; s < GEN_SPLIT; s++)
        gen += g_gen_partial[(size_t)s * BB * DM + i];
    const float comb = g_combined[i];
    out[i] = gen + __bfloat162float(__float2bfloat16(comb));
}

// ---------------------------------------------------------------------------
extern "C" void kernel_launch(void* const* d_in, const int* in_sizes, int n_in,
                              void* d_out, int out_size) {
    const float* xf   = (const float*)d_in[0];   // cycle_curve_data [B,L,D] = [B,F]
    const float* cyc  = (const float*)d_in[1];   // cycle_numbers   [B,1]
    const float* dkp  = (const float*)d_in[2];   // DKP_embeddings  [B,768]
    const float* Wg1  = (const float*)d_in[3];   // [13569,256]
    const float* bg1  = (const float*)d_in[4];   // [256]
    const float* Wg2  = (const float*)d_in[5];   // [256,8]
    const float* bg2  = (const float*)d_in[6];   // [8]
    const float* We   = (const float*)d_in[7];   // [8,12800,128]
    const float* be   = (const float*)d_in[8];   // [8,128]
    const float* Wgen = (const float*)d_in[9];   // [12800,128]
    const float* bgen = (const float*)d_in[10];  // [128]
    float* out = (float*)d_out;

    init_zero_kernel<<<(BB * DM + 255) / 256, 256>>>();
    gate_gemm_kernel<<<dim3(BB / 32, GATE_SPLIT), 256>>>(xf, cyc, dkp, Wg1);
    gate_epilogue_kernel<<<BB / 8, 256>>>(bg1, Wg2, bg2);
    general_gemm_kernel<<<dim3(BB / 32, GEN_SPLIT), 256>>>(xf, Wgen);
    expert_gemm_kernel<<<dim3(BB / 32, NE), 256>>>(xf, We, be);
    finalize_kernel<<<(BB * DM + 255) / 256, 256>>>(bgen, out);
}